// round 2
// baseline (speedup 1.0000x reference)
#include <cuda_runtime.h>

#define BB   512
#define VV   50257
#define TT   2048
#define TOPK 50
#define NT   512
#define NBINS 4096
#define CAP  2048
#define MASKW 1571

// ---- shared memory layout (bytes) ----
#define SLOG_BYTES (50264 * 4)                 // 201056 (V padded to 8)
#define MASK_OFF   (SLOG_BYTES)                // 201056
#define MASK_BYTES (1600 * 4)                  // 6400
#define UN_OFF     (MASK_OFF + MASK_BYTES)     // 207456 (hist 4096*i32 | ckey 2048*u64)
#define UN_BYTES   (16384)
#define GSUM_OFF   (UN_OFF + UN_BYTES)         // 223840
#define GSUM_BYTES (512 * 4)
#define SCR_OFF    (GSUM_OFF + GSUM_BYTES)     // 225888

struct Scr {
    float wred[16];
    float sval[TOPK];
    int   sidx[TOPK];
    float M, Z, pivot, M0, Zk, invtemp;
    int   tbin, ccount, pividx;
};

static const int SMEM_BYTES = SCR_OFF + (int)sizeof(Scr);

__device__ __forceinline__ unsigned fkey(float x) {
    unsigned u = __float_as_uint(x);
    return (u & 0x80000000u) ? ~u : (u | 0x80000000u);
}

__global__ void __launch_bounds__(NT, 1)
decode_kernel(const float* __restrict__ logits,
              const int*   __restrict__ prev,
              const float* __restrict__ randu,
              const float* __restrict__ tempp,
              const float* __restrict__ toppp,
              const float* __restrict__ rpp,
              float*  probsF, double* probsD,
              long long* idx64, float* idxF, double* idxD)
{
    extern __shared__ char smem[];
    float*               slog = (float*)smem;
    unsigned*            mask = (unsigned*)(smem + MASK_OFF);
    int*                 hist = (int*)(smem + UN_OFF);
    unsigned long long*  ckey = (unsigned long long*)(smem + UN_OFF);
    int*                 gsum = (int*)(smem + GSUM_OFF);
    Scr*                 S    = (Scr*)(smem + SCR_OFF);

    const int b   = blockIdx.x;
    const int tid = threadIdx.x;

    // ---- init mask + histogram ----
    for (int i = tid; i < MASKW; i += NT) mask[i] = 0u;
    for (int i = tid; i < NBINS; i += NT) hist[i] = 0;
    if (tid == 0) S->ccount = 0;
    __syncthreads();

    // ---- penalty bitmask from previous tokens (bounds-guarded) ----
    const int* prow = prev + (long long)b * TT;
    for (int i = tid; i < TT; i += NT) {
        unsigned tok = (unsigned)prow[i];
        if (tok < (unsigned)VV)
            atomicOr(&mask[tok >> 5], 1u << (tok & 31));
    }
    __syncthreads();

    // ---- load + penalize logits into smem, compute row max ----
    const float rp = __ldg(rpp);
    const float* lrow = logits + (long long)b * VV;
    float lmax = -3.4e38f;
    #pragma unroll 4
    for (int v = tid; v < VV; v += NT) {
        float x = __ldg(lrow + v);
        if ((mask[v >> 5] >> (v & 31)) & 1u) x = (x < 0.f) ? x * rp : x / rp;
        slog[v] = x;
        lmax = fmaxf(lmax, x);
    }
    #pragma unroll
    for (int off = 16; off; off >>= 1)
        lmax = fmaxf(lmax, __shfl_xor_sync(0xffffffffu, lmax, off));
    if ((tid & 31) == 0) S->wred[tid >> 5] = lmax;
    __syncthreads();
    if (tid == 0) {
        float m = S->wred[0];
        #pragma unroll
        for (int j = 1; j < 16; j++) m = fmaxf(m, S->wred[j]);
        S->M = m;
    }
    __syncthreads();
    const float M = S->M;
    __syncthreads();

    // ---- Z = sum exp(l - M) and value-ordered histogram ----
    float zs = 0.f;
    #pragma unroll 4
    for (int v = tid; v < VV; v += NT) {
        float x = slog[v];
        zs += __expf(x - M);
        atomicAdd(&hist[fkey(x) >> 20], 1);
    }
    #pragma unroll
    for (int off = 16; off; off >>= 1)
        zs += __shfl_xor_sync(0xffffffffu, zs, off);
    if ((tid & 31) == 0) S->wred[tid >> 5] = zs;
    __syncthreads();                 // also orders all hist atomics
    if (tid == 0) {
        float z = 0.f;
        #pragma unroll
        for (int j = 0; j < 16; j++) z += S->wred[j];
        S->Z = z;
    }

    // ---- threshold bin: smallest bin with suffix-count >= TOPK ----
    {
        int g = 0;
        #pragma unroll
        for (int j = 0; j < 8; j++) g += hist[tid * 8 + j];
        gsum[tid] = g;
    }
    __syncthreads();
    if (tid < 32) {
        int s = 0;
        #pragma unroll
        for (int j = 0; j < 16; j++) s += gsum[tid * 16 + j];
        int suf = s;
        #pragma unroll
        for (int off = 1; off < 32; off <<= 1) {
            int o = __shfl_down_sync(0xffffffffu, suf, off);
            if (tid + off < 32) suf += o;
        }
        unsigned ball = __ballot_sync(0xffffffffu, suf >= TOPK);
        int gsel = 31 - __clz(ball);
        int above = __shfl_sync(0xffffffffu, suf, (gsel + 1) & 31);
        if (gsel == 31) above = 0;

        const int gb = gsel * 128;
        int s2 = 0;
        #pragma unroll
        for (int j = 0; j < 4; j++) s2 += hist[gb + tid * 4 + j];
        int suf2 = s2;
        #pragma unroll
        for (int off = 1; off < 32; off <<= 1) {
            int o = __shfl_down_sync(0xffffffffu, suf2, off);
            if (tid + off < 32) suf2 += o;
        }
        unsigned ball2 = __ballot_sync(0xffffffffu, (above + suf2) >= TOPK);
        int l2 = 31 - __clz(ball2);
        int above2 = __shfl_sync(0xffffffffu, suf2, (l2 + 1) & 31);
        if (l2 == 31) above2 = 0;
        above2 += above;
        if (tid == 0) {
            int acc = above2;
            int tb = gb + l2 * 4;
            for (int j = 3; j >= 0; --j) {
                acc += hist[gb + l2 * 4 + j];
                if (acc >= TOPK) { tb = gb + l2 * 4 + j; break; }
            }
            S->tbin = tb;
        }
    }
    __syncthreads();
    const unsigned tbin = (unsigned)S->tbin;
    __syncthreads();   // all hist reads done before ckey overwrites the union

    // ---- gather candidates (value above threshold bin) ----
    for (int v = tid; v < VV; v += NT) {
        unsigned k = fkey(slog[v]);
        if ((k >> 20) >= tbin) {
            int pos = atomicAdd(&S->ccount, 1);
            if (pos < CAP)
                ckey[pos] = ((unsigned long long)k << 32) |
                            (unsigned long long)(0xFFFFFFFFu - (unsigned)v);
        }
    }
    __syncthreads();
    const int ncand = min(S->ccount, CAP);

    // ---- warp 0: exact top-50 (value desc, index asc) ----
    if (tid < 32) {
        for (int k = 0; k < TOPK; ++k) {
            unsigned long long best = 0ull;
            for (int i = tid; i < ncand; i += 32) {
                unsigned long long c = ckey[i];
                if (c > best) best = c;
            }
            #pragma unroll
            for (int off = 16; off; off >>= 1) {
                unsigned long long o = __shfl_xor_sync(0xffffffffu, best, off);
                if (o > best) best = o;
            }
            for (int i = tid; i < ncand; i += 32)
                if (ckey[i] == best) ckey[i] = 0ull;
            if (tid == 0) {
                unsigned hk = (unsigned)(best >> 32);
                unsigned ob = (hk & 0x80000000u) ? (hk ^ 0x80000000u) : ~hk;
                S->sval[k] = __uint_as_float(ob);
                S->sidx[k] = (int)(0xFFFFFFFFu - (unsigned)(best & 0xFFFFFFFFull));
            }
            __syncwarp();
        }
    }
    __syncthreads();

    // ---- thread 0: top-p cutoff, Zk, Gumbel argmax ----
    if (tid == 0) {
        const float Z    = S->Z;
        const float topp = __ldg(toppp);
        const float temp = fmaxf(__ldg(tempp), 1e-5f);
        const float invt = 1.f / temp;

        float c = 0.f; int cnt = 0;
        for (int k = 0; k < TOPK; ++k) {
            c += expf(S->sval[k] - M) / Z;
            if (c <= topp) cnt++; else break;
        }
        int m = cnt < 1 ? 1 : cnt;          // rank 0 always kept
        if (m > TOPK) m = TOPK;

        const float M0 = S->sval[0];
        float Zk = 0.f;
        for (int k = 0; k < m; ++k) Zk += expf((S->sval[k] - M0) * invt);

        const float* urow = randu + (long long)b * VV;
        float bestr = -1.f; int besti = VV;
        for (int k = 0; k < m; ++k) {
            float pk = expf((S->sval[k] - M0) * invt) / Zk;
            float q  = -logf(__ldg(urow + S->sidx[k]));
            float r  = pk / q;
            if (r > bestr || (r == bestr && S->sidx[k] < besti)) {
                bestr = r; besti = S->sidx[k];
            }
        }
        if (idx64) idx64[b] = (long long)besti;
        if (idxF)  idxF[b]  = (float)besti;
        if (idxD)  idxD[b]  = (double)besti;

        S->pivot   = S->sval[m - 1];
        S->pividx  = S->sidx[m - 1];
        S->M0      = M0;
        S->Zk      = Zk;
        S->invtemp = invt;
    }
    __syncthreads();

    // ---- write probs (removed tokens are exactly 0, matching fp32 underflow) ----
    const float pivot  = S->pivot;
    const int   pividx = S->pividx;
    const float M0     = S->M0;
    const float invZk  = 1.f / S->Zk;
    const float invt   = S->invtemp;

    if (probsF) {
        float* orow = probsF + (long long)b * VV;
        #pragma unroll 4
        for (int v = tid; v < VV; v += NT) {
            float x = slog[v];
            bool kept = (x > pivot) || (x == pivot && v <= pividx);
            orow[v] = kept ? __expf((x - M0) * invt) * invZk : 0.f;
        }
    } else if (probsD) {
        double* orow = probsD + (long long)b * VV;
        #pragma unroll 4
        for (int v = tid; v < VV; v += NT) {
            float x = slog[v];
            bool kept = (x > pivot) || (x == pivot && v <= pividx);
            orow[v] = kept ? (double)(__expf((x - M0) * invt) * invZk) : 0.0;
        }
    }
}

extern "C" void kernel_launch(void* const* d_in, const int* in_sizes, int n_in,
                              void* d_out, int out_size)
{
    const float* logits = (const float*)d_in[0];
    const int*   prev   = (const int*)d_in[1];
    const float* randu  = (const float*)d_in[2];
    const float* temp   = (const float*)d_in[3];
    const float* topp   = (const float*)d_in[4];
    const float* rp     = (const float*)d_in[5];

    float*  probsF = nullptr; double* probsD = nullptr;
    long long* idx64 = nullptr; float* idxF = nullptr; double* idxD = nullptr;

    const long long BV = (long long)BB * VV;
    const long long oz = (long long)out_size;

    if (oz == BB + BV) {
        // tuple concat, single 4-byte dtype (idx cast to float32) — crash-safe
        // for any element size >= 4B; if dtype is f64 we get rel_err evidence.
        idxF = (float*)d_out; probsF = (float*)d_out + BB;
    } else if (oz == 2 * BB + BV) {
        // float32 buffer, idx stored as raw int64 words (2 floats each)
        idx64 = (long long*)d_out; probsF = (float*)d_out + 2 * BB;
    } else if (oz == BB + BV / 2) {
        // int64-element buffer: idx int64, probs packed as float pairs
        idx64 = (long long*)d_out; probsF = (float*)((long long*)d_out + BB);
    } else if (oz == BV) {
        probsF = (float*)d_out;
    } else if (oz == BB) {
        idx64 = (long long*)d_out;
    } else if (oz == 8LL * BB + 4LL * BV) {
        // byte-count buffer
        idx64 = (long long*)d_out; probsF = (float*)((char*)d_out + 8LL * BB);
    } else {
        // fallback: float32 concat
        idxF = (float*)d_out; probsF = (float*)d_out + BB;
    }

    cudaFuncSetAttribute(decode_kernel,
                         cudaFuncAttributeMaxDynamicSharedMemorySize, SMEM_BYTES);
    decode_kernel<<<BB, NT, SMEM_BYTES>>>(logits, prev, randu, temp, topp, rp,
                                          probsF, probsD, idx64, idxF, idxD);
}

// round 3
// speedup vs baseline: 1.2569x; 1.2569x over previous
#include <cuda_runtime.h>

#define BB   512
#define VV   50257
#define TT   2048
#define TOPK 50
#define NT   512
#define CAP  4096
#define MASKW 1571
#define MASKP 1600

struct Scr {
    float wmax[16];
    float wsum[16];
    float sval[TOPK];
    int   sidx[TOPK];
    unsigned long long gkey[2];
    float M, Z, M0, Zk, invt, delta;
    int   m, ncand;
};

__device__ __forceinline__ unsigned fkey(float x) {
    unsigned u = __float_as_uint(x);
    return (u & 0x80000000u) ? ~u : (u | 0x80000000u);
}

__global__ void __launch_bounds__(NT, 3)
decode_kernel(const float* __restrict__ logits,
              const int*   __restrict__ prev,
              const float* __restrict__ randu,
              const float* __restrict__ tempp,
              const float* __restrict__ toppp,
              const float* __restrict__ rpp,
              float*  probsF, double* probsD,
              long long* idx64, float* idxF, double* idxD)
{
    __shared__ unsigned           mask[MASKP];
    __shared__ unsigned long long ckey[CAP];
    __shared__ Scr S;

    const int b   = blockIdx.x;
    const int tid = threadIdx.x;
    const int lane = tid & 31;
    const int wrp  = tid >> 5;

    // ---- zero-fill probs row FIRST (stores overlap all later work) ----
    float*  orowF = probsF ? probsF + (long long)b * VV : nullptr;
    double* orowD = probsD ? probsD + (long long)b * VV : nullptr;
    if (orowF) {
        #pragma unroll 4
        for (int v = tid; v < VV; v += NT) orowF[v] = 0.f;
    } else if (orowD) {
        #pragma unroll 4
        for (int v = tid; v < VV; v += NT) orowD[v] = 0.0;
    }

    // ---- init mask ----
    for (int i = tid; i < MASKP; i += NT) mask[i] = 0u;
    if (tid == 0) { S.ncand = 0; S.delta = 9.f; }
    __syncthreads();

    // ---- penalty bitmask ----
    const int* prow = prev + (long long)b * TT;
    for (int i = tid; i < TT; i += NT) {
        unsigned tok = (unsigned)prow[i];
        if (tok < (unsigned)VV)
            atomicOr(&mask[tok >> 5], 1u << (tok & 31));
    }
    __syncthreads();

    // ---- pass 1: online softmax (max + Z) over penalized logits ----
    const float rp = __ldg(rpp);
    const float* lrow = logits + (long long)b * VV;
    float m = -3.4e38f, s = 0.f;
    #pragma unroll 4
    for (int v = tid; v < VV; v += NT) {
        float x = __ldg(lrow + v);
        if ((mask[v >> 5] >> (v & 31)) & 1u) x = (x < 0.f) ? x * rp : x / rp;
        if (x <= m) {
            s += __expf(x - m);
        } else {
            s = s * __expf(m - x) + 1.f;
            m = x;
        }
    }
    #pragma unroll
    for (int off = 16; off; off >>= 1) {
        float om = __shfl_xor_sync(0xffffffffu, m, off);
        float os = __shfl_xor_sync(0xffffffffu, s, off);
        float nm = fmaxf(m, om);
        s = s * __expf(m - nm) + os * __expf(om - nm);
        m = nm;
    }
    if (lane == 0) { S.wmax[wrp] = m; S.wsum[wrp] = s; }
    __syncthreads();
    if (tid == 0) {
        float gm = S.wmax[0];
        #pragma unroll
        for (int j = 1; j < 16; j++) gm = fmaxf(gm, S.wmax[j]);
        float gz = 0.f;
        #pragma unroll
        for (int j = 0; j < 16; j++) gz += S.wsum[j] * __expf(S.wmax[j] - gm);
        S.M = gm; S.Z = gz;
    }
    __syncthreads();
    const float M = S.M;

    // ---- pass 2: adaptive candidate gather (x >= M - delta), L2-hot reread ----
    int ncand = 0;
    for (int iter = 0; iter < 8; ++iter) {
        const float t = M - S.delta;
        #pragma unroll 4
        for (int v = tid; v < VV; v += NT) {
            float x = __ldg(lrow + v);
            if ((mask[v >> 5] >> (v & 31)) & 1u) x = (x < 0.f) ? x * rp : x / rp;
            if (x >= t) {
                int pos = atomicAdd(&S.ncand, 1);
                if (pos < CAP)
                    ckey[pos] = ((unsigned long long)fkey(x) << 32) |
                                (unsigned long long)(0xFFFFFFFFu - (unsigned)v);
            }
        }
        __syncthreads();
        ncand = S.ncand;
        if (ncand >= TOPK && ncand <= CAP) break;
        if (tid == 0) {
            S.ncand = 0;
            S.delta = (ncand < TOPK) ? S.delta * 2.f : S.delta * 0.55f;
        }
        __syncthreads();
    }
    const int nc = min(ncand, CAP);
    const int kk = min(TOPK, nc);

    // ---- warp 0: exact top-kk (value desc, index asc) ----
    if (tid < 32) {
        for (int k = 0; k < kk; ++k) {
            unsigned long long best = 0ull;
            for (int i = tid; i < nc; i += 32) {
                unsigned long long c = ckey[i];
                if (c > best) best = c;
            }
            #pragma unroll
            for (int off = 16; off; off >>= 1) {
                unsigned long long o = __shfl_xor_sync(0xffffffffu, best, off);
                if (o > best) best = o;
            }
            for (int i = tid; i < nc; i += 32)
                if (ckey[i] == best) ckey[i] = 0ull;
            if (tid == 0) {
                unsigned hk = (unsigned)(best >> 32);
                unsigned ob = (hk & 0x80000000u) ? (hk ^ 0x80000000u) : ~hk;
                S.sval[k] = __uint_as_float(ob);
                S.sidx[k] = (int)(0xFFFFFFFFu - (unsigned)(best & 0xFFFFFFFFull));
            }
            __syncwarp();
        }
    }
    __syncthreads();

    // ---- thread 0: top-p cutoff, Zk ----
    if (tid == 0) {
        const float Z    = S.Z;
        const float topp = __ldg(toppp);
        const float temp = fmaxf(__ldg(tempp), 1e-5f);
        const float invt = 1.f / temp;

        float c = 0.f; int cnt = 0;
        for (int k = 0; k < kk; ++k) {
            c += expf(S.sval[k] - M) / Z;
            if (c <= topp) cnt++; else break;
        }
        int mm = cnt < 1 ? 1 : cnt;
        if (mm > kk) mm = kk;

        const float M0 = S.sval[0];
        float Zk = 0.f;
        for (int k = 0; k < mm; ++k) Zk += expf((S.sval[k] - M0) * invt);

        S.m = mm; S.M0 = M0; S.Zk = Zk; S.invt = invt;
        S.gkey[0] = 0ull; S.gkey[1] = 0ull;
    }
    __syncthreads();

    // ---- parallel Gumbel argmax over m kept tokens (threads 0..63) ----
    const int   mm   = S.m;
    const float M0   = S.M0;
    const float Zk   = S.Zk;
    const float invt = S.invt;

    if (tid < 64) {
        unsigned long long key = 0ull;
        if (tid < mm) {
            float pk = expf((S.sval[tid] - M0) * invt) / Zk;
            float u  = __ldg(randu + (long long)b * VV + S.sidx[tid]);
            float q  = -logf(u);
            float r  = pk / q;
            key = ((unsigned long long)fkey(r) << 32) |
                  (unsigned long long)(0xFFFFFFFFu - (unsigned)S.sidx[tid]);
        }
        #pragma unroll
        for (int off = 16; off; off >>= 1) {
            unsigned long long o = __shfl_xor_sync(0xffffffffu, key, off);
            if (o > key) key = o;
        }
        if (lane == 0) S.gkey[wrp] = key;
    }
    __syncthreads();

    if (tid == 0) {
        unsigned long long best = S.gkey[0] > S.gkey[1] ? S.gkey[0] : S.gkey[1];
        int besti = (int)(0xFFFFFFFFu - (unsigned)(best & 0xFFFFFFFFull));
        if (idx64) idx64[b] = (long long)besti;
        if (idxF)  idxF[b]  = (float)besti;
        if (idxD)  idxD[b]  = (double)besti;
    }

    // ---- scatter the m nonzero probabilities ----
    if (tid < mm) {
        float pk = expf((S.sval[tid] - M0) * invt) / Zk;
        if (orowF) orowF[S.sidx[tid]] = pk;
        else if (orowD) orowD[S.sidx[tid]] = (double)pk;
    }
}

extern "C" void kernel_launch(void* const* d_in, const int* in_sizes, int n_in,
                              void* d_out, int out_size)
{
    const float* logits = (const float*)d_in[0];
    const int*   prev   = (const int*)d_in[1];
    const float* randu  = (const float*)d_in[2];
    const float* temp   = (const float*)d_in[3];
    const float* topp   = (const float*)d_in[4];
    const float* rp     = (const float*)d_in[5];

    float*  probsF = nullptr; double* probsD = nullptr;
    long long* idx64 = nullptr; float* idxF = nullptr; double* idxD = nullptr;

    const long long BV = (long long)BB * VV;
    const long long oz = (long long)out_size;

    if (oz == BB + BV) {
        // tuple concat, float32 elements (idx cast to float) — the passing layout
        idxF = (float*)d_out; probsF = (float*)d_out + BB;
    } else if (oz == 2 * BB + BV) {
        idx64 = (long long*)d_out; probsF = (float*)d_out + 2 * BB;
    } else if (oz == BB + BV / 2) {
        idx64 = (long long*)d_out; probsF = (float*)((long long*)d_out + BB);
    } else if (oz == BV) {
        probsF = (float*)d_out;
    } else if (oz == BB) {
        idx64 = (long long*)d_out;
    } else if (oz == 8LL * BB + 4LL * BV) {
        idx64 = (long long*)d_out; probsF = (float*)((char*)d_out + 8LL * BB);
    } else {
        idxF = (float*)d_out; probsF = (float*)d_out + BB;
    }

    decode_kernel<<<BB, NT>>>(logits, prev, randu, temp, topp, rp,
                              probsF, probsD, idx64, idxF, idxD);
}

// round 4
// speedup vs baseline: 2.6085x; 2.0753x over previous
#include <cuda_runtime.h>

#define BB   512
#define VV   50257
#define TT   2048
#define TOPK 50
#define NT   512
#define CAP  2048
#define MASKP 1600

struct Scr {
    float wred[16];
    float sval[TOPK];
    int   sidx[TOPK];
    unsigned long long gkey[2];
    float M, Z, M0, Zk, invt, delta;
    int   m, ncand;
};

__device__ __forceinline__ unsigned fkey(float x) {
    unsigned u = __float_as_uint(x);
    return (u & 0x80000000u) ? ~u : (u | 0x80000000u);
}

__device__ __forceinline__ float penal(float x, bool mk, float rp, float invrp) {
    return mk ? (x < 0.f ? x * rp : x * invrp) : x;
}

__device__ __forceinline__ void push_cand(unsigned long long* ckey, int* pnc,
                                          float x, int v) {
    int pos = atomicAdd(pnc, 1);
    if (pos < CAP)
        ckey[pos] = ((unsigned long long)fkey(x) << 32) |
                    (unsigned long long)(0xFFFFFFFFu - (unsigned)v);
}

__global__ void __launch_bounds__(NT, 4)
decode_kernel(const float* __restrict__ logits,
              const int*   __restrict__ prev,
              const float* __restrict__ randu,
              const float* __restrict__ tempp,
              const float* __restrict__ toppp,
              const float* __restrict__ rpp,
              float*  probsF, double* probsD,
              long long* idx64, float* idxF, double* idxD)
{
    __shared__ unsigned           mask[MASKP];
    __shared__ unsigned long long ckey[CAP];
    __shared__ Scr S;

    const int b    = blockIdx.x;
    const int tid  = threadIdx.x;
    const int lane = tid & 31;
    const int wrp  = tid >> 5;

    // row start element-offset mod 4 == b mod 4 (VV % 4 == 1)
    const int p     = (4 - (b & 3)) & 3;
    const int nvec  = (VV - p) >> 2;
    const int vtail = p + (nvec << 2);

    const float* lrow  = logits + (long long)b * VV;
    float*  orowF = probsF ? probsF + (long long)b * VV : nullptr;
    double* orowD = probsD ? probsD + (long long)b * VV : nullptr;

    // ---- zero-fill probs row first (stores overlap later work) ----
    if (orowF) {
        const float4 z4 = make_float4(0.f, 0.f, 0.f, 0.f);
        for (int k = tid; k < nvec; k += NT)
            *(float4*)(orowF + p + 4 * k) = z4;
        for (int v = tid; v < p; v += NT)          orowF[v] = 0.f;
        for (int v = vtail + tid; v < VV; v += NT) orowF[v] = 0.f;
    } else if (orowD) {
        for (int v = tid; v < VV; v += NT) orowD[v] = 0.0;
    }

    // ---- init ----
    for (int i = tid; i < MASKP; i += NT) mask[i] = 0u;
    if (tid == 0) { S.ncand = 0; S.delta = 9.f; }
    __syncthreads();

    // ---- penalty bitmask ----
    const int* prow = prev + (long long)b * TT;
    for (int i = tid; i < TT; i += NT) {
        unsigned tok = (unsigned)prow[i];
        if (tok < (unsigned)VV)
            atomicOr(&mask[tok >> 5], 1u << (tok & 31));
    }
    __syncthreads();

    const float rp    = __ldg(rpp);
    const float invrp = 1.f / rp;

    // ---- pass A: block max of penalized logits (vectorized, branch-free) ----
    float m = -3.4e38f;
    for (int k = tid; k < nvec; k += NT) {
        const int v0 = p + 4 * k;
        float4 X = __ldg((const float4*)(lrow + v0));
        unsigned bits = __funnelshift_r(mask[v0 >> 5], mask[(v0 >> 5) + 1], v0 & 31) & 0xFu;
        X.x = penal(X.x, bits & 1u, rp, invrp);
        X.y = penal(X.y, bits & 2u, rp, invrp);
        X.z = penal(X.z, bits & 4u, rp, invrp);
        X.w = penal(X.w, bits & 8u, rp, invrp);
        m = fmaxf(m, fmaxf(fmaxf(X.x, X.y), fmaxf(X.z, X.w)));
    }
    for (int v = tid; v < p; v += NT) {
        float x = penal(__ldg(lrow + v), (mask[v >> 5] >> (v & 31)) & 1u, rp, invrp);
        m = fmaxf(m, x);
    }
    for (int v = vtail + tid; v < VV; v += NT) {
        float x = penal(__ldg(lrow + v), (mask[v >> 5] >> (v & 31)) & 1u, rp, invrp);
        m = fmaxf(m, x);
    }
    #pragma unroll
    for (int off = 16; off; off >>= 1)
        m = fmaxf(m, __shfl_xor_sync(0xffffffffu, m, off));
    if (lane == 0) S.wred[wrp] = m;
    __syncthreads();
    if (tid == 0) {
        float gm = S.wred[0];
        #pragma unroll
        for (int j = 1; j < 16; j++) gm = fmaxf(gm, S.wred[j]);
        S.M = gm;
    }
    __syncthreads();
    const float M = S.M;

    // ---- pass B: fused Z-sum + candidate gather (x >= M - delta) ----
    float t  = M - S.delta;
    float zs = 0.f;
    for (int k = tid; k < nvec; k += NT) {
        const int v0 = p + 4 * k;
        float4 X = __ldg((const float4*)(lrow + v0));
        unsigned bits = __funnelshift_r(mask[v0 >> 5], mask[(v0 >> 5) + 1], v0 & 31) & 0xFu;
        X.x = penal(X.x, bits & 1u, rp, invrp);
        X.y = penal(X.y, bits & 2u, rp, invrp);
        X.z = penal(X.z, bits & 4u, rp, invrp);
        X.w = penal(X.w, bits & 8u, rp, invrp);
        zs += __expf(X.x - M) + __expf(X.y - M) + __expf(X.z - M) + __expf(X.w - M);
        if (X.x >= t) push_cand(ckey, &S.ncand, X.x, v0);
        if (X.y >= t) push_cand(ckey, &S.ncand, X.y, v0 + 1);
        if (X.z >= t) push_cand(ckey, &S.ncand, X.z, v0 + 2);
        if (X.w >= t) push_cand(ckey, &S.ncand, X.w, v0 + 3);
    }
    for (int v = tid; v < p; v += NT) {
        float x = penal(__ldg(lrow + v), (mask[v >> 5] >> (v & 31)) & 1u, rp, invrp);
        zs += __expf(x - M);
        if (x >= t) push_cand(ckey, &S.ncand, x, v);
    }
    for (int v = vtail + tid; v < VV; v += NT) {
        float x = penal(__ldg(lrow + v), (mask[v >> 5] >> (v & 31)) & 1u, rp, invrp);
        zs += __expf(x - M);
        if (x >= t) push_cand(ckey, &S.ncand, x, v);
    }
    #pragma unroll
    for (int off = 16; off; off >>= 1)
        zs += __shfl_xor_sync(0xffffffffu, zs, off);
    if (lane == 0) S.wred[wrp] = zs;
    __syncthreads();
    if (tid == 0) {
        float gz = 0.f;
        #pragma unroll
        for (int j = 0; j < 16; j++) gz += S.wred[j];
        S.Z = gz;
    }
    __syncthreads();

    // ---- adaptive retry (gather only; L2-hot reread; rarely taken) ----
    int ncand = S.ncand;
    for (int it = 0; it < 6; ++it) {
        if (ncand >= TOPK && ncand <= CAP) break;
        __syncthreads();
        if (tid == 0) {
            S.delta = (ncand < TOPK) ? S.delta * 2.f : S.delta * 0.5f;
            S.ncand = 0;
        }
        __syncthreads();
        t = M - S.delta;
        for (int k = tid; k < nvec; k += NT) {
            const int v0 = p + 4 * k;
            float4 X = __ldg((const float4*)(lrow + v0));
            unsigned bits = __funnelshift_r(mask[v0 >> 5], mask[(v0 >> 5) + 1], v0 & 31) & 0xFu;
            X.x = penal(X.x, bits & 1u, rp, invrp);
            X.y = penal(X.y, bits & 2u, rp, invrp);
            X.z = penal(X.z, bits & 4u, rp, invrp);
            X.w = penal(X.w, bits & 8u, rp, invrp);
            if (X.x >= t) push_cand(ckey, &S.ncand, X.x, v0);
            if (X.y >= t) push_cand(ckey, &S.ncand, X.y, v0 + 1);
            if (X.z >= t) push_cand(ckey, &S.ncand, X.z, v0 + 2);
            if (X.w >= t) push_cand(ckey, &S.ncand, X.w, v0 + 3);
        }
        for (int v = tid; v < p; v += NT) {
            float x = penal(__ldg(lrow + v), (mask[v >> 5] >> (v & 31)) & 1u, rp, invrp);
            if (x >= t) push_cand(ckey, &S.ncand, x, v);
        }
        for (int v = vtail + tid; v < VV; v += NT) {
            float x = penal(__ldg(lrow + v), (mask[v >> 5] >> (v & 31)) & 1u, rp, invrp);
            if (x >= t) push_cand(ckey, &S.ncand, x, v);
        }
        __syncthreads();
        ncand = S.ncand;
    }
    const int nc = min(ncand, CAP);
    const int kk = min(TOPK, nc);

    // ---- warp 0: exact top-kk (value desc, index asc) ----
    if (tid < 32) {
        for (int k = 0; k < kk; ++k) {
            unsigned long long best = 0ull;
            for (int i = tid; i < nc; i += 32) {
                unsigned long long c = ckey[i];
                if (c > best) best = c;
            }
            #pragma unroll
            for (int off = 16; off; off >>= 1) {
                unsigned long long o = __shfl_xor_sync(0xffffffffu, best, off);
                if (o > best) best = o;
            }
            for (int i = tid; i < nc; i += 32)
                if (ckey[i] == best) ckey[i] = 0ull;
            if (tid == 0) {
                unsigned hk = (unsigned)(best >> 32);
                unsigned ob = (hk & 0x80000000u) ? (hk ^ 0x80000000u) : ~hk;
                S.sval[k] = __uint_as_float(ob);
                S.sidx[k] = (int)(0xFFFFFFFFu - (unsigned)(best & 0xFFFFFFFFull));
            }
            __syncwarp();
        }
    }
    __syncthreads();

    // ---- thread 0: top-p cutoff, Zk ----
    if (tid == 0) {
        const float Z    = S.Z;
        const float topp = __ldg(toppp);
        const float temp = fmaxf(__ldg(tempp), 1e-5f);
        const float invt = 1.f / temp;

        float c = 0.f; int cnt = 0;
        for (int k = 0; k < kk; ++k) {
            c += expf(S.sval[k] - M) / Z;
            if (c <= topp) cnt++; else break;
        }
        int mm = cnt < 1 ? 1 : cnt;
        if (mm > kk) mm = kk;

        const float M0 = S.sval[0];
        float Zk = 0.f;
        for (int k = 0; k < mm; ++k) Zk += expf((S.sval[k] - M0) * invt);

        S.m = mm; S.M0 = M0; S.Zk = Zk; S.invt = invt;
        S.gkey[0] = 0ull; S.gkey[1] = 0ull;
    }
    __syncthreads();

    // ---- parallel Gumbel argmax over kept tokens (threads 0..63) ----
    const int   mm   = S.m;
    const float M0   = S.M0;
    const float Zk   = S.Zk;
    const float invt = S.invt;

    if (tid < 64) {
        unsigned long long key = 0ull;
        if (tid < mm) {
            float pk = expf((S.sval[tid] - M0) * invt) / Zk;
            float u  = __ldg(randu + (long long)b * VV + S.sidx[tid]);
            float q  = -logf(u);
            float r  = pk / q;
            key = ((unsigned long long)fkey(r) << 32) |
                  (unsigned long long)(0xFFFFFFFFu - (unsigned)S.sidx[tid]);
        }
        #pragma unroll
        for (int off = 16; off; off >>= 1) {
            unsigned long long o = __shfl_xor_sync(0xffffffffu, key, off);
            if (o > key) key = o;
        }
        if (lane == 0) S.gkey[wrp] = key;
    }
    __syncthreads();

    if (tid == 0) {
        unsigned long long best = S.gkey[0] > S.gkey[1] ? S.gkey[0] : S.gkey[1];
        int besti = (int)(0xFFFFFFFFu - (unsigned)(best & 0xFFFFFFFFull));
        if (idx64) idx64[b] = (long long)besti;
        if (idxF)  idxF[b]  = (float)besti;
        if (idxD)  idxD[b]  = (double)besti;
    }

    // ---- scatter the mm nonzero probabilities ----
    if (tid < mm) {
        float pk = expf((S.sval[tid] - M0) * invt) / Zk;
        if (orowF) orowF[S.sidx[tid]] = pk;
        else if (orowD) orowD[S.sidx[tid]] = (double)pk;
    }
}

extern "C" void kernel_launch(void* const* d_in, const int* in_sizes, int n_in,
                              void* d_out, int out_size)
{
    const float* logits = (const float*)d_in[0];
    const int*   prev   = (const int*)d_in[1];
    const float* randu  = (const float*)d_in[2];
    const float* temp   = (const float*)d_in[3];
    const float* topp   = (const float*)d_in[4];
    const float* rp     = (const float*)d_in[5];

    float*  probsF = nullptr; double* probsD = nullptr;
    long long* idx64 = nullptr; float* idxF = nullptr; double* idxD = nullptr;

    const long long BV = (long long)BB * VV;
    const long long oz = (long long)out_size;

    if (oz == BB + BV) {
        // tuple concat, float32 elements (idx cast to float) — the passing layout
        idxF = (float*)d_out; probsF = (float*)d_out + BB;
    } else if (oz == 2 * BB + BV) {
        idx64 = (long long*)d_out; probsF = (float*)d_out + 2 * BB;
    } else if (oz == BB + BV / 2) {
        idx64 = (long long*)d_out; probsF = (float*)((long long*)d_out + BB);
    } else if (oz == BV) {
        probsF = (float*)d_out;
    } else if (oz == BB) {
        idx64 = (long long*)d_out;
    } else if (oz == 8LL * BB + 4LL * BV) {
        idx64 = (long long*)d_out; probsF = (float*)((char*)d_out + 8LL * BB);
    } else {
        idxF = (float*)d_out; probsF = (float*)d_out + BB;
    }

    decode_kernel<<<BB, NT>>>(logits, prev, randu, temp, topp, rp,
                              probsF, probsD, idx64, idxF, idxD);
}